// round 16
// baseline (speedup 1.0000x reference)
#include <cuda_runtime.h>
#include <cuda_bf16.h>
#include <math.h>

// Problem shape (fixed): encoder_output [C,K,H] fp32, W [H,H] fp32.
#define C_DIM 512
#define K_DIM 64
#define H_DIM 1024
#define H4 (H_DIM / 4)

// GEMM: M=512, N=1024, K=1024 as 3xBF16 mma.sync. CTA 128x128, BK=32.
// split-K=8 -> grid 256 CTAs (~2/SM), 2-stage cp.async, 2 CTAs/SM.
#define SPLITK 8
#define KSEG (H_DIM / SPLITK)   // 128
#define BK 32
#define NITER (KSEG / BK)       // 4
#define STAGES 2
#define AROW 72                 // smem row stride in bf16: 32 hi | 32 lo | 8 pad
#define STAGE_ELEMS (128 * AROW)
#define SMEM_BYTES (STAGES * 2 * STAGE_ELEMS * 2)   // 73728

// Cluster route: 4 CTAs per capsule, each owns a 256-h quarter.
#define RQ 4
#define QH (H_DIM / RQ)         // 256
#define QH4 (QH / 4)            // 64
#define SLAB_BYTES (K_DIM * QH * 4)   // 65536

// -------------------------------------------------------------------------
// Scratch (device globals only; zero-initialized at module load)
// -------------------------------------------------------------------------
__device__ __align__(16) __nv_bfloat16 g_shi [C_DIM * H_DIM];
__device__ __align__(16) __nv_bfloat16 g_slo [C_DIM * H_DIM];
__device__ __align__(16) __nv_bfloat16 g_chi [C_DIM * H_DIM];
__device__ __align__(16) __nv_bfloat16 g_clo [C_DIM * H_DIM];
__device__ __align__(16) __nv_bfloat16 g_wahi[H_DIM * H_DIM];  // bf16(W)   [n][k]
__device__ __align__(16) __nv_bfloat16 g_walo[H_DIM * H_DIM];
__device__ __align__(16) __nv_bfloat16 g_wbhi[H_DIM * H_DIM];  // bf16(W^T) [n][k]
__device__ __align__(16) __nv_bfloat16 g_wblo[H_DIM * H_DIM];
__device__ __align__(16) float g_part[SPLITK][C_DIM * H_DIM];
__device__ __align__(16) float g_b   [C_DIM * K_DIM];

// -------------------------------------------------------------------------
// Helpers
// -------------------------------------------------------------------------
__device__ __forceinline__ void bf16_split(float x, __nv_bfloat16& h, __nv_bfloat16& l) {
    h = __float2bfloat16(x);
    l = __float2bfloat16(x - __bfloat162float(h));
}

__device__ __forceinline__ void mma_bf16(float c[4],
                                         unsigned a0, unsigned a1, unsigned a2, unsigned a3,
                                         unsigned b0, unsigned b1) {
    asm volatile(
        "mma.sync.aligned.m16n8k16.row.col.f32.bf16.bf16.f32 "
        "{%0,%1,%2,%3}, {%4,%5,%6,%7}, {%8,%9}, {%0,%1,%2,%3};"
        : "+f"(c[0]), "+f"(c[1]), "+f"(c[2]), "+f"(c[3])
        : "r"(a0), "r"(a1), "r"(a2), "r"(a3), "r"(b0), "r"(b1));
}

__device__ __forceinline__ void ldsm_x4(unsigned& r0, unsigned& r1,
                                        unsigned& r2, unsigned& r3, unsigned addr) {
    asm volatile("ldmatrix.sync.aligned.m8n8.x4.shared.b16 {%0,%1,%2,%3}, [%4];"
                 : "=r"(r0), "=r"(r1), "=r"(r2), "=r"(r3) : "r"(addr));
}

__device__ __forceinline__ void cp16(void* smem, const void* gmem) {
    unsigned s = (unsigned)__cvta_generic_to_shared(smem);
    asm volatile("cp.async.cg.shared.global [%0], [%1], 16;" :: "r"(s), "l"(gmem));
}
__device__ __forceinline__ void cp_commit() { asm volatile("cp.async.commit_group;"); }
__device__ __forceinline__ void cp_wait0()  { asm volatile("cp.async.wait_group 0;" ::: "memory"); }

__device__ __forceinline__ unsigned mapa_rank(unsigned addr, unsigned rank) {
    unsigned r;
    asm("mapa.shared::cluster.u32 %0, %1, %2;" : "=r"(r) : "r"(addr), "r"(rank));
    return r;
}
__device__ __forceinline__ float ld_dsmem_f32(unsigned addr) {
    float v;
    asm volatile("ld.shared::cluster.f32 %0, [%1];" : "=f"(v) : "r"(addr));
    return v;
}
__device__ __forceinline__ void cluster_sync_() {
    asm volatile("barrier.cluster.arrive.aligned;" ::: "memory");
    asm volatile("barrier.cluster.wait.aligned;" ::: "memory");
}

// -------------------------------------------------------------------------
// W preprocessing: bf16 hi/lo planes of W (for s@W^T) and of W^T (for c@W).
// -------------------------------------------------------------------------
__global__ __launch_bounds__(256) void split_w_kernel(const float* __restrict__ W) {
    __shared__ __nv_bfloat16 th[32][33], tl[32][33];
    const int tx = threadIdx.x & 31, ty = threadIdx.x >> 5;
    const int bx = blockIdx.x, by = blockIdx.y;

#pragma unroll
    for (int s = 0; s < 4; ++s) {
        const int r = by * 32 + ty + s * 8;
        const int c = bx * 32 + tx;
        float v = __ldg(&W[r * H_DIM + c]);
        __nv_bfloat16 h, l;
        bf16_split(v, h, l);
        g_wahi[r * H_DIM + c] = h;
        g_walo[r * H_DIM + c] = l;
        th[ty + s * 8][tx] = h;
        tl[ty + s * 8][tx] = l;
    }
    __syncthreads();
#pragma unroll
    for (int s = 0; s < 4; ++s) {
        const int r2 = bx * 32 + ty + s * 8;   // row of W^T
        const int c2 = by * 32 + tx;
        g_wbhi[r2 * H_DIM + c2] = th[tx][ty + s * 8];
        g_wblo[r2 * H_DIM + c2] = tl[tx][ty + s * 8];
    }
}

// -------------------------------------------------------------------------
// Kernel 1: iteration-1 weighted sum (uniform d=1/64) -> s hi/lo planes; b<-0.
// grid (512, 2), block 128.
// -------------------------------------------------------------------------
__global__ __launch_bounds__(128) void ws_uniform_kernel(const float* __restrict__ x) {
    const int c = blockIdx.x;
    const int t = blockIdx.y * 128 + threadIdx.x;
    const float4* xp = reinterpret_cast<const float4*>(x) + (size_t)c * K_DIM * H4;

    float4 acc = make_float4(0.f, 0.f, 0.f, 0.f);
#pragma unroll 8
    for (int k = 0; k < K_DIM; ++k) {
        float4 v = __ldg(&xp[k * H4 + t]);
        acc.x += v.x; acc.y += v.y; acc.z += v.z; acc.w += v.w;
    }
    const float inv = 1.0f / (float)K_DIM;
    float o[4] = {acc.x * inv, acc.y * inv, acc.z * inv, acc.w * inv};

    __nv_bfloat16 h[4], l[4];
#pragma unroll
    for (int q = 0; q < 4; ++q) bf16_split(o[q], h[q], l[q]);
    reinterpret_cast<uint2*>(g_shi)[c * H4 + t] = *reinterpret_cast<uint2*>(h);
    reinterpret_cast<uint2*>(g_slo)[c * H4 + t] = *reinterpret_cast<uint2*>(l);

    if (blockIdx.y == 0 && threadIdx.x < K_DIM) g_b[c * K_DIM + threadIdx.x] = 0.0f;
}

// -------------------------------------------------------------------------
// 3xBF16 tensor-core GEMM with ldmatrix fragment loads (round-12 proven form).
//   g_part[z][m,n] = partial sum_k (Ahi+Alo)[m,k] * (Bhi+Blo)[n,k]
// -------------------------------------------------------------------------
__global__ __launch_bounds__(256, 2) void gemm_bf16_kernel(
        const __nv_bfloat16* __restrict__ Ahi, const __nv_bfloat16* __restrict__ Alo,
        const __nv_bfloat16* __restrict__ Bhi, const __nv_bfloat16* __restrict__ Blo) {
    extern __shared__ __align__(16) __nv_bfloat16 sm[];
    __nv_bfloat16* sA = sm;
    __nv_bfloat16* sB = sm + STAGES * STAGE_ELEMS;

    const int tid  = threadIdx.x;
    const int w    = tid >> 5, lane = tid & 31;
    const int g    = lane >> 2, tig = lane & 3;
    const int wm   = w >> 2;
    const int wn   = w & 3;
    const int m0   = blockIdx.y * 128;
    const int n0   = blockIdx.x * 128;
    const int kbeg = blockIdx.z * KSEG;

    const unsigned sA_base = (unsigned)__cvta_generic_to_shared(sA);
    const unsigned sB_base = (unsigned)__cvta_generic_to_shared(sB);
    const int a_row  = lane & 15;
    const int a_koff = (lane >> 4) << 3;
    unsigned a_addr[4];
#pragma unroll
    for (int i = 0; i < 4; ++i)
        a_addr[i] = sA_base + 2u * ((wm * 64 + i * 16 + a_row) * AROW + a_koff);
    const int b_row  = (lane & 7) | ((lane & 16) >> 1);
    const int b_koff = (lane & 8);
    unsigned b_addr[2];
#pragma unroll
    for (int jp = 0; jp < 2; ++jp)
        b_addr[jp] = sB_base + 2u * ((wn * 32 + jp * 16 + b_row) * AROW + b_koff);

    float acc[4][4][4];
#pragma unroll
    for (int i = 0; i < 4; ++i)
#pragma unroll
        for (int j = 0; j < 4; ++j)
#pragma unroll
            for (int q = 0; q < 4; ++q) acc[i][j][q] = 0.f;

    auto issue = [&](int it, int buf) {
        const int kw = kbeg + it * BK;
        __nv_bfloat16* aS = sA + buf * STAGE_ELEMS;
        __nv_bfloat16* bS = sB + buf * STAGE_ELEMS;
        const int q = tid & 3, r0 = tid >> 2;
#pragma unroll
        for (int rr = 0; rr < 2; ++rr) {
            const int row = r0 + rr * 64;
            const size_t goA = (size_t)(m0 + row) * H_DIM + kw + q * 8;
            cp16(&aS[row * AROW + q * 8],      Ahi + goA);
            cp16(&aS[row * AROW + 32 + q * 8], Alo + goA);
            const size_t goB = (size_t)(n0 + row) * H_DIM + kw + q * 8;
            cp16(&bS[row * AROW + q * 8],      Bhi + goB);
            cp16(&bS[row * AROW + 32 + q * 8], Blo + goB);
        }
        cp_commit();
    };

    issue(0, 0);
    for (int it = 0; it < NITER; ++it) {
        const int buf = it & 1;
        cp_wait0();
        __syncthreads();
        if (it + 1 < NITER) issue(it + 1, buf ^ 1);

        const unsigned stage_off = (unsigned)(buf * STAGE_ELEMS * 2);
#pragma unroll
        for (int ks = 0; ks < BK; ks += 16) {
            const unsigned ks_off = stage_off + 2u * ks;
            unsigned ahi[4][4], alo[4][4];
#pragma unroll
            for (int i = 0; i < 4; ++i) {
                ldsm_x4(ahi[i][0], ahi[i][1], ahi[i][2], ahi[i][3],
                        a_addr[i] + ks_off);
                ldsm_x4(alo[i][0], alo[i][1], alo[i][2], alo[i][3],
                        a_addr[i] + ks_off + 64u);
            }
#pragma unroll
            for (int jp = 0; jp < 2; ++jp) {
                unsigned bh[4], bl[4];
                ldsm_x4(bh[0], bh[1], bh[2], bh[3], b_addr[jp] + ks_off);
                ldsm_x4(bl[0], bl[1], bl[2], bl[3], b_addr[jp] + ks_off + 64u);
                const int j0 = jp * 2, j1 = jp * 2 + 1;
#pragma unroll
                for (int i = 0; i < 4; ++i) {
                    mma_bf16(acc[i][j0], ahi[i][0], ahi[i][1], ahi[i][2], ahi[i][3], bh[0], bh[1]);
                    mma_bf16(acc[i][j0], ahi[i][0], ahi[i][1], ahi[i][2], ahi[i][3], bl[0], bl[1]);
                    mma_bf16(acc[i][j0], alo[i][0], alo[i][1], alo[i][2], alo[i][3], bh[0], bh[1]);
                    mma_bf16(acc[i][j1], ahi[i][0], ahi[i][1], ahi[i][2], ahi[i][3], bh[2], bh[3]);
                    mma_bf16(acc[i][j1], ahi[i][0], ahi[i][1], ahi[i][2], ahi[i][3], bl[2], bl[3]);
                    mma_bf16(acc[i][j1], alo[i][0], alo[i][1], alo[i][2], alo[i][3], bh[2], bh[3]);
                }
            }
        }
        __syncthreads();
    }

    float* P = g_part[blockIdx.z];
#pragma unroll
    for (int i = 0; i < 4; ++i) {
        const int m = m0 + wm * 64 + i * 16;
#pragma unroll
        for (int j = 0; j < 4; ++j) {
            const int n = n0 + wn * 32 + j * 8 + 2 * tig;
            *reinterpret_cast<float2*>(&P[(size_t)(m + g)     * H_DIM + n]) =
                make_float2(acc[i][j][0], acc[i][j][1]);
            *reinterpret_cast<float2*>(&P[(size_t)(m + g + 8) * H_DIM + n]) =
                make_float2(acc[i][j][2], acc[i][j][3]);
        }
    }
}

// -------------------------------------------------------------------------
// Squash: v = sum of SPLITK partials; c = v*(ns/(1+ns))/sqrt(ns+eps).
// WANT_SPLIT=1 emits bf16 hi/lo planes of c; =0 writes fp32 output.
// -------------------------------------------------------------------------
template <int WANT_SPLIT>
__global__ __launch_bounds__(256) void squash_kernel(float* __restrict__ outp) {
    const int c = blockIdx.x;
    const int t = threadIdx.x;
    const int lane = t & 31, wid = t >> 5;

    float4 v = make_float4(0.f, 0.f, 0.f, 0.f);
#pragma unroll
    for (int z = 0; z < SPLITK; ++z) {
        float4 a = reinterpret_cast<const float4*>(g_part[z])[c * H4 + t];
        v.x += a.x; v.y += a.y; v.z += a.z; v.w += a.w;
    }

    float p = v.x * v.x + v.y * v.y + v.z * v.z + v.w * v.w;
#pragma unroll
    for (int off = 16; off; off >>= 1) p += __shfl_down_sync(0xffffffffu, p, off);

    __shared__ float wsum[8];
    if (lane == 0) wsum[wid] = p;
    __syncthreads();
    float ns = 0.f;
#pragma unroll
    for (int wq = 0; wq < 8; ++wq) ns += wsum[wq];

    const float scale = (ns / (1.0f + ns)) * rsqrtf(ns + 1e-9f);
    float o[4] = {v.x * scale, v.y * scale, v.z * scale, v.w * scale};

    if (WANT_SPLIT) {
        __nv_bfloat16 h[4], l[4];
#pragma unroll
        for (int q = 0; q < 4; ++q) bf16_split(o[q], h[q], l[q]);
        reinterpret_cast<uint2*>(g_chi)[c * H4 + t] = *reinterpret_cast<uint2*>(h);
        reinterpret_cast<uint2*>(g_clo)[c * H4 + t] = *reinterpret_cast<uint2*>(l);
    } else {
        reinterpret_cast<float4*>(outp)[c * H4 + t] = make_float4(o[0], o[1], o[2], o[3]);
    }
}

// -------------------------------------------------------------------------
// Cluster fused routing step (single x pass):
// 4-CTA cluster per capsule; CTA q owns h-quarter [q*256, q*256+256).
//   0. read OLD g_b into registers (BEFORE any cluster barrier -> no race
//      with rank 0's later write-back)
//   1. cp.async x slab (64k x 256h fp32 = 64KB) into smem; u quarter from parts
//   2. partial b[k] = slab . u_quarter  (warp-per-8k)
//   3. DSMEM exchange of 64 partials across the 4 ranks -> full b
//   4. b = b_old + inc ; softmax -> d (identical in every rank)
//   5. s_quarter = sum_k d[k]*slab[k][:] -> bf16 hi/lo planes (from smem!)
// -------------------------------------------------------------------------
__global__ __launch_bounds__(256) __cluster_dims__(RQ, 1, 1)
void route_cluster_kernel(const float* __restrict__ x) {
    extern __shared__ __align__(16) float slab[];   // [K_DIM][QH]
    __shared__ float ush[QH];
    __shared__ float bpart[K_DIM];                  // this rank's partial dots
    __shared__ float bsh[K_DIM];
    __shared__ float dsh[K_DIM];

    const int q = blockIdx.x;        // cluster rank / h-quarter
    const int c = blockIdx.y;        // capsule
    const int t = threadIdx.x;
    const int lane = t & 31, wid = t >> 5;
    const int h0 = q * QH;

    // Step 0: read OLD b before any cluster barrier (orders against rank 0's
    // write-back, which happens only after cluster_sync #1).
    float bold = 0.f;
    if (t < K_DIM) bold = g_b[c * K_DIM + t];

    // u quarter = sum of split-K partials over this h range
    if (t < QH4) {
        float4 uv = make_float4(0.f, 0.f, 0.f, 0.f);
#pragma unroll
        for (int z = 0; z < SPLITK; ++z) {
            float4 a = reinterpret_cast<const float4*>(g_part[z])[c * H4 + q * QH4 + t];
            uv.x += a.x; uv.y += a.y; uv.z += a.z; uv.w += a.w;
        }
        reinterpret_cast<float4*>(ush)[t] = uv;
    }

    // slab load: 64 rows x 64 16B-chunks = 4096 cp16, 16 per thread
    const float* xc = x + (size_t)c * K_DIM * H_DIM + h0;
#pragma unroll
    for (int i = 0; i < 16; ++i) {
        const int slot = t + 256 * i;
        const int k = slot >> 6, c4 = slot & 63;
        cp16(&slab[k * QH + c4 * 4], xc + (size_t)k * H_DIM + c4 * 4);
    }
    cp_commit();
    cp_wait0();
    __syncthreads();

    // Phase A: warp owns 8 k's; per-lane 8-elem partial, one reduce per k
    float ureg[8];
#pragma unroll
    for (int j = 0; j < 8; ++j) ureg[j] = ush[lane + 32 * j];
    const int k0 = wid * 8;
#pragma unroll
    for (int kk = 0; kk < 8; ++kk) {
        const float* row = &slab[(k0 + kk) * QH];
        float d = 0.f;
#pragma unroll
        for (int j = 0; j < 8; ++j) d += row[lane + 32 * j] * ureg[j];
#pragma unroll
        for (int off = 16; off; off >>= 1) d += __shfl_down_sync(0xffffffffu, d, off);
        if (lane == 0) bpart[k0 + kk] = d;
    }

    // Exchange partials across the 4 cluster ranks (DSMEM)
    cluster_sync_();
    if (t < K_DIM) {
        const unsigned local = (unsigned)__cvta_generic_to_shared(&bpart[t]);
        float bb = bold;
#pragma unroll
        for (unsigned r = 0; r < RQ; ++r)
            bb += ld_dsmem_f32(mapa_rank(local, r));
        if (q == 0) g_b[c * K_DIM + t] = bb;
        bsh[t] = bb;
    }
    __syncthreads();

    // Softmax over K=64 (warp 0)
    if (t < 32) {
        float b0 = bsh[t], b1 = bsh[t + 32];
        float m = fmaxf(b0, b1);
#pragma unroll
        for (int off = 16; off; off >>= 1) m = fmaxf(m, __shfl_xor_sync(0xffffffffu, m, off));
        float e0 = expf(b0 - m), e1 = expf(b1 - m);
        float ss = e0 + e1;
#pragma unroll
        for (int off = 16; off; off >>= 1) ss += __shfl_xor_sync(0xffffffffu, ss, off);
        float inv = 1.0f / ss;
        dsh[t]      = e0 * inv;
        dsh[t + 32] = e1 * inv;
    }
    __syncthreads();

    // Phase B: s_quarter from smem slab (thread t owns h = h0 + t)
    float acc = 0.f;
#pragma unroll 8
    for (int k = 0; k < K_DIM; ++k)
        acc += dsh[k] * slab[k * QH + t];

    __nv_bfloat16 h, l;
    bf16_split(acc, h, l);
    g_shi[(size_t)c * H_DIM + h0 + t] = h;
    g_slo[(size_t)c * H_DIM + h0 + t] = l;

    // No CTA may exit while peers might still read its bpart via DSMEM.
    cluster_sync_();
}

// -------------------------------------------------------------------------
// Launch
// -------------------------------------------------------------------------
extern "C" void kernel_launch(void* const* d_in, const int* in_sizes, int n_in,
                              void* d_out, int out_size) {
    const float* x = (const float*)d_in[0];   // [512,64,1024]
    const float* W = (const float*)d_in[1];   // [1024,1024]
    float* out = (float*)d_out;               // [512,1024]

    __nv_bfloat16 *shi, *slo, *chi, *clo, *wahi, *walo, *wbhi, *wblo;
    cudaGetSymbolAddress((void**)&shi,  g_shi);
    cudaGetSymbolAddress((void**)&slo,  g_slo);
    cudaGetSymbolAddress((void**)&chi,  g_chi);
    cudaGetSymbolAddress((void**)&clo,  g_clo);
    cudaGetSymbolAddress((void**)&wahi, g_wahi);
    cudaGetSymbolAddress((void**)&walo, g_walo);
    cudaGetSymbolAddress((void**)&wbhi, g_wbhi);
    cudaGetSymbolAddress((void**)&wblo, g_wblo);

    cudaFuncSetAttribute(gemm_bf16_kernel,
                         cudaFuncAttributeMaxDynamicSharedMemorySize, SMEM_BYTES);
    cudaFuncSetAttribute(route_cluster_kernel,
                         cudaFuncAttributeMaxDynamicSharedMemorySize, SLAB_BYTES);

    const dim3 gemm_grid(H_DIM / 128, C_DIM / 128, SPLITK);  // (8, 4, 8) = 256
    const dim3 route_grid(RQ, C_DIM);                        // (4, 512) clusters

    split_w_kernel<<<dim3(32, 32), 256>>>(W);
    ws_uniform_kernel<<<dim3(C_DIM, 2), 128>>>(x);

    for (int iter = 0; iter < 3; ++iter) {
        // c_hat = s @ W^T   (B = bf16(W) rows [n][k]) -> g_part
        gemm_bf16_kernel<<<gemm_grid, 256, SMEM_BYTES>>>(shi, slo, wahi, walo);
        if (iter == 2)
            squash_kernel<0><<<C_DIM, 256>>>(out);
        else
            squash_kernel<1><<<C_DIM, 256>>>(nullptr);

        if (iter < 2) {
            // t = c @ W   (B = bf16(W^T) rows [n][k]) -> g_part
            gemm_bf16_kernel<<<gemm_grid, 256, SMEM_BYTES>>>(chi, clo, wbhi, wblo);
            route_cluster_kernel<<<route_grid, 256, SLAB_BYTES>>>(x);
        }
    }
}

// round 17
// speedup vs baseline: 1.4038x; 1.4038x over previous
#include <cuda_runtime.h>
#include <cuda_bf16.h>
#include <math.h>

// Problem shape (fixed): encoder_output [C,K,H] fp32, W [H,H] fp32.
#define C_DIM 512
#define K_DIM 64
#define H_DIM 1024
#define H4 (H_DIM / 4)

// GEMM: M=512, N=1024, K=1024 as 3xBF16 mma.sync.
// CTA tile 128x64, BK=32, split-K=4 -> grid (16,4,4)=256 CTAs, 2 CTAs/SM.
#define SPLITK 4
#define KSEG (H_DIM / SPLITK)   // 256
#define BK 32
#define NITER (KSEG / BK)       // 8
#define STAGES 2
#define AROW 72                 // smem row stride in bf16: 32 hi | 32 lo | 8 pad
#define A_STAGE (128 * AROW)    // A: 128 rows
#define B_STAGE (64 * AROW)     // B: 64 rows
#define SMEM_BYTES (STAGES * (A_STAGE + B_STAGE) * 2)   // 55296

// -------------------------------------------------------------------------
// Scratch (device globals only; zero-initialized at module load)
// -------------------------------------------------------------------------
__device__ __align__(16) __nv_bfloat16 g_shi [C_DIM * H_DIM];
__device__ __align__(16) __nv_bfloat16 g_slo [C_DIM * H_DIM];
__device__ __align__(16) __nv_bfloat16 g_chi [C_DIM * H_DIM];
__device__ __align__(16) __nv_bfloat16 g_clo [C_DIM * H_DIM];
__device__ __align__(16) __nv_bfloat16 g_wahi[H_DIM * H_DIM];  // bf16(W)   [n][k]
__device__ __align__(16) __nv_bfloat16 g_walo[H_DIM * H_DIM];
__device__ __align__(16) __nv_bfloat16 g_wbhi[H_DIM * H_DIM];  // bf16(W^T) [n][k]
__device__ __align__(16) __nv_bfloat16 g_wblo[H_DIM * H_DIM];
__device__ __align__(16) float g_part[SPLITK][C_DIM * H_DIM];
__device__ __align__(16) float g_b   [C_DIM * K_DIM];

// -------------------------------------------------------------------------
// Helpers
// -------------------------------------------------------------------------
__device__ __forceinline__ void bf16_split(float x, __nv_bfloat16& h, __nv_bfloat16& l) {
    h = __float2bfloat16(x);
    l = __float2bfloat16(x - __bfloat162float(h));
}

__device__ __forceinline__ void mma_bf16(float c[4],
                                         unsigned a0, unsigned a1, unsigned a2, unsigned a3,
                                         unsigned b0, unsigned b1) {
    asm volatile(
        "mma.sync.aligned.m16n8k16.row.col.f32.bf16.bf16.f32 "
        "{%0,%1,%2,%3}, {%4,%5,%6,%7}, {%8,%9}, {%0,%1,%2,%3};"
        : "+f"(c[0]), "+f"(c[1]), "+f"(c[2]), "+f"(c[3])
        : "r"(a0), "r"(a1), "r"(a2), "r"(a3), "r"(b0), "r"(b1));
}

__device__ __forceinline__ void ldsm_x4(unsigned& r0, unsigned& r1,
                                        unsigned& r2, unsigned& r3, unsigned addr) {
    asm volatile("ldmatrix.sync.aligned.m8n8.x4.shared.b16 {%0,%1,%2,%3}, [%4];"
                 : "=r"(r0), "=r"(r1), "=r"(r2), "=r"(r3) : "r"(addr));
}

__device__ __forceinline__ void cp16(void* smem, const void* gmem) {
    unsigned s = (unsigned)__cvta_generic_to_shared(smem);
    asm volatile("cp.async.cg.shared.global [%0], [%1], 16;" :: "r"(s), "l"(gmem));
}
__device__ __forceinline__ void cp_commit() { asm volatile("cp.async.commit_group;"); }
__device__ __forceinline__ void cp_wait0()  { asm volatile("cp.async.wait_group 0;" ::: "memory"); }

// -------------------------------------------------------------------------
// W preprocessing: bf16 hi/lo planes of W (for s@W^T) and of W^T (for c@W).
// -------------------------------------------------------------------------
__global__ __launch_bounds__(256) void split_w_kernel(const float* __restrict__ W) {
    __shared__ __nv_bfloat16 th[32][33], tl[32][33];
    const int tx = threadIdx.x & 31, ty = threadIdx.x >> 5;
    const int bx = blockIdx.x, by = blockIdx.y;

#pragma unroll
    for (int s = 0; s < 4; ++s) {
        const int r = by * 32 + ty + s * 8;
        const int c = bx * 32 + tx;
        float v = __ldg(&W[r * H_DIM + c]);
        __nv_bfloat16 h, l;
        bf16_split(v, h, l);
        g_wahi[r * H_DIM + c] = h;
        g_walo[r * H_DIM + c] = l;
        th[ty + s * 8][tx] = h;
        tl[ty + s * 8][tx] = l;
    }
    __syncthreads();
#pragma unroll
    for (int s = 0; s < 4; ++s) {
        const int r2 = bx * 32 + ty + s * 8;   // row of W^T
        const int c2 = by * 32 + tx;
        g_wbhi[r2 * H_DIM + c2] = th[tx][ty + s * 8];
        g_wblo[r2 * H_DIM + c2] = tl[tx][ty + s * 8];
    }
}

// -------------------------------------------------------------------------
// Kernel 1: iteration-1 weighted sum (uniform d=1/64) -> s hi/lo planes; b<-0.
// grid (512, 2), block 128.
// -------------------------------------------------------------------------
__global__ __launch_bounds__(128) void ws_uniform_kernel(const float* __restrict__ x) {
    const int c = blockIdx.x;
    const int t = blockIdx.y * 128 + threadIdx.x;
    const float4* xp = reinterpret_cast<const float4*>(x) + (size_t)c * K_DIM * H4;

    float4 acc = make_float4(0.f, 0.f, 0.f, 0.f);
#pragma unroll 16
    for (int k = 0; k < K_DIM; ++k) {
        float4 v = __ldg(&xp[k * H4 + t]);
        acc.x += v.x; acc.y += v.y; acc.z += v.z; acc.w += v.w;
    }
    const float inv = 1.0f / (float)K_DIM;
    float o[4] = {acc.x * inv, acc.y * inv, acc.z * inv, acc.w * inv};

    __nv_bfloat16 h[4], l[4];
#pragma unroll
    for (int q = 0; q < 4; ++q) bf16_split(o[q], h[q], l[q]);
    reinterpret_cast<uint2*>(g_shi)[c * H4 + t] = *reinterpret_cast<uint2*>(h);
    reinterpret_cast<uint2*>(g_slo)[c * H4 + t] = *reinterpret_cast<uint2*>(l);

    if (blockIdx.y == 0 && threadIdx.x < K_DIM) g_b[c * K_DIM + threadIdx.x] = 0.0f;
}

// -------------------------------------------------------------------------
// 3xBF16 tensor-core GEMM, CTA tile 128x64, ldmatrix fragment loads.
//   g_part[z][m,n] = partial sum_k (Ahi+Alo)[m,k] * (Bhi+Blo)[n,k]
// 256 thr = 8 warps (4m x 2n, warp tile 32x32), BK=32, 2-stage cp.async.
// smem rows: [hi(32) | lo(32) | pad(8)] stride AROW=72 bf16 (conflict-free).
// -------------------------------------------------------------------------
__global__ __launch_bounds__(256, 2) void gemm_bf16_kernel(
        const __nv_bfloat16* __restrict__ Ahi, const __nv_bfloat16* __restrict__ Alo,
        const __nv_bfloat16* __restrict__ Bhi, const __nv_bfloat16* __restrict__ Blo) {
    extern __shared__ __align__(16) __nv_bfloat16 sm[];
    __nv_bfloat16* sA = sm;                              // STAGES * A_STAGE
    __nv_bfloat16* sB = sm + STAGES * A_STAGE;           // STAGES * B_STAGE

    const int tid  = threadIdx.x;
    const int w    = tid >> 5, lane = tid & 31;
    const int g    = lane >> 2, tig = lane & 3;
    const int wm   = w >> 1;          // 0..3  (32 rows each)
    const int wn   = w & 1;           // 0..1  (32 cols each)
    const int m0   = blockIdx.y * 128;
    const int n0   = blockIdx.x * 64;
    const int kbeg = blockIdx.z * KSEG;

    const unsigned sA_base = (unsigned)__cvta_generic_to_shared(sA);
    const unsigned sB_base = (unsigned)__cvta_generic_to_shared(sB);
    const int a_row  = lane & 15;
    const int a_koff = (lane >> 4) << 3;
    unsigned a_addr[2];
#pragma unroll
    for (int i = 0; i < 2; ++i)
        a_addr[i] = sA_base + 2u * ((wm * 32 + i * 16 + a_row) * AROW + a_koff);
    const int b_row  = (lane & 7) | ((lane & 16) >> 1);
    const int b_koff = (lane & 8);
    unsigned b_addr[2];
#pragma unroll
    for (int jp = 0; jp < 2; ++jp)
        b_addr[jp] = sB_base + 2u * ((wn * 32 + jp * 16 + b_row) * AROW + b_koff);

    float acc[2][4][4];
#pragma unroll
    for (int i = 0; i < 2; ++i)
#pragma unroll
        for (int j = 0; j < 4; ++j)
#pragma unroll
            for (int q = 0; q < 4; ++q) acc[i][j][q] = 0.f;

    auto issue = [&](int it, int buf) {
        const int kw = kbeg + it * BK;
        __nv_bfloat16* aS = sA + buf * A_STAGE;
        __nv_bfloat16* bS = sB + buf * B_STAGE;
        const int q = tid & 3, r0 = tid >> 2;       // q: 16B chunk (8 bf16)
        // A: 128 rows x 32 k, hi+lo (2 rows per thread)
#pragma unroll
        for (int rr = 0; rr < 2; ++rr) {
            const int row = r0 + rr * 64;
            const size_t goA = (size_t)(m0 + row) * H_DIM + kw + q * 8;
            cp16(&aS[row * AROW + q * 8],      Ahi + goA);
            cp16(&aS[row * AROW + 32 + q * 8], Alo + goA);
        }
        // B: 64 rows x 32 k, hi+lo (1 row per thread)
        {
            const size_t goB = (size_t)(n0 + r0) * H_DIM + kw + q * 8;
            cp16(&bS[r0 * AROW + q * 8],      Bhi + goB);
            cp16(&bS[r0 * AROW + 32 + q * 8], Blo + goB);
        }
        cp_commit();
    };

    issue(0, 0);
    for (int it = 0; it < NITER; ++it) {
        const int buf = it & 1;
        cp_wait0();
        __syncthreads();
        if (it + 1 < NITER) issue(it + 1, buf ^ 1);

        const unsigned a_off = (unsigned)(buf * A_STAGE * 2);
        const unsigned b_off = (unsigned)(buf * B_STAGE * 2);
#pragma unroll
        for (int ks = 0; ks < BK; ks += 16) {
            const unsigned ksb = 2u * ks;
            unsigned ahi[2][4], alo[2][4];
#pragma unroll
            for (int i = 0; i < 2; ++i) {
                ldsm_x4(ahi[i][0], ahi[i][1], ahi[i][2], ahi[i][3],
                        a_addr[i] + a_off + ksb);            // hi plane
                ldsm_x4(alo[i][0], alo[i][1], alo[i][2], alo[i][3],
                        a_addr[i] + a_off + ksb + 64u);      // lo plane
            }
#pragma unroll
            for (int jp = 0; jp < 2; ++jp) {
                unsigned bh[4], bl[4];
                ldsm_x4(bh[0], bh[1], bh[2], bh[3], b_addr[jp] + b_off + ksb);
                ldsm_x4(bl[0], bl[1], bl[2], bl[3], b_addr[jp] + b_off + ksb + 64u);
                const int j0 = jp * 2, j1 = jp * 2 + 1;
#pragma unroll
                for (int i = 0; i < 2; ++i) {
                    mma_bf16(acc[i][j0], ahi[i][0], ahi[i][1], ahi[i][2], ahi[i][3], bh[0], bh[1]);
                    mma_bf16(acc[i][j0], ahi[i][0], ahi[i][1], ahi[i][2], ahi[i][3], bl[0], bl[1]);
                    mma_bf16(acc[i][j0], alo[i][0], alo[i][1], alo[i][2], alo[i][3], bh[0], bh[1]);
                    mma_bf16(acc[i][j1], ahi[i][0], ahi[i][1], ahi[i][2], ahi[i][3], bh[2], bh[3]);
                    mma_bf16(acc[i][j1], ahi[i][0], ahi[i][1], ahi[i][2], ahi[i][3], bl[2], bl[3]);
                    mma_bf16(acc[i][j1], alo[i][0], alo[i][1], alo[i][2], alo[i][3], bh[2], bh[3]);
                }
            }
        }
        __syncthreads();
    }

    float* P = g_part[blockIdx.z];
#pragma unroll
    for (int i = 0; i < 2; ++i) {
        const int m = m0 + wm * 32 + i * 16;
#pragma unroll
        for (int j = 0; j < 4; ++j) {
            const int n = n0 + wn * 32 + j * 8 + 2 * tig;
            *reinterpret_cast<float2*>(&P[(size_t)(m + g)     * H_DIM + n]) =
                make_float2(acc[i][j][0], acc[i][j][1]);
            *reinterpret_cast<float2*>(&P[(size_t)(m + g + 8) * H_DIM + n]) =
                make_float2(acc[i][j][2], acc[i][j][3]);
        }
    }
}

// -------------------------------------------------------------------------
// Squash: v = sum of SPLITK partials; c = v*(ns/(1+ns))/sqrt(ns+eps).
// WANT_SPLIT=1 emits bf16 hi/lo planes of c; =0 writes fp32 output.
// -------------------------------------------------------------------------
template <int WANT_SPLIT>
__global__ __launch_bounds__(256) void squash_kernel(float* __restrict__ outp) {
    const int c = blockIdx.x;
    const int t = threadIdx.x;
    const int lane = t & 31, wid = t >> 5;

    float4 v = make_float4(0.f, 0.f, 0.f, 0.f);
#pragma unroll
    for (int z = 0; z < SPLITK; ++z) {
        float4 a = reinterpret_cast<const float4*>(g_part[z])[c * H4 + t];
        v.x += a.x; v.y += a.y; v.z += a.z; v.w += a.w;
    }

    float p = v.x * v.x + v.y * v.y + v.z * v.z + v.w * v.w;
#pragma unroll
    for (int off = 16; off; off >>= 1) p += __shfl_down_sync(0xffffffffu, p, off);

    __shared__ float wsum[8];
    if (lane == 0) wsum[wid] = p;
    __syncthreads();
    float ns = 0.f;
#pragma unroll
    for (int wq = 0; wq < 8; ++wq) ns += wsum[wq];

    const float scale = (ns / (1.0f + ns)) * rsqrtf(ns + 1e-9f);
    float o[4] = {v.x * scale, v.y * scale, v.z * scale, v.w * scale};

    if (WANT_SPLIT) {
        __nv_bfloat16 h[4], l[4];
#pragma unroll
        for (int q = 0; q < 4; ++q) bf16_split(o[q], h[q], l[q]);
        reinterpret_cast<uint2*>(g_chi)[c * H4 + t] = *reinterpret_cast<uint2*>(h);
        reinterpret_cast<uint2*>(g_clo)[c * H4 + t] = *reinterpret_cast<uint2*>(l);
    } else {
        reinterpret_cast<float4*>(outp)[c * H4 + t] = make_float4(o[0], o[1], o[2], o[3]);
    }
}

// -------------------------------------------------------------------------
// Fused routing step (round-12 proven form):
//   t = sum partials (c@W) -> smem ; b += x.t (warp-per-8k, accumulate-then-
//   reduce) ; d = softmax(b) ; s = sum_k d*x -> bf16 hi/lo planes
// -------------------------------------------------------------------------
__global__ __launch_bounds__(256) void fused_route_kernel(const float* __restrict__ x) {
    const int c = blockIdx.x;
    const int t = threadIdx.x;
    const int lane = t & 31, wid = t >> 5;

    __shared__ float4 tsh[H4];       // t vector (4 KB)
    __shared__ float bsh[K_DIM];
    __shared__ float dsh[K_DIM];

    // t = sum of split-K partials, cached in smem
    float4 tv = make_float4(0.f, 0.f, 0.f, 0.f);
#pragma unroll
    for (int z = 0; z < SPLITK; ++z) {
        float4 a = reinterpret_cast<const float4*>(g_part[z])[c * H4 + t];
        tv.x += a.x; tv.y += a.y; tv.z += a.z; tv.w += a.w;
    }
    tsh[t] = tv;
    __syncthreads();

    const float4* xp = reinterpret_cast<const float4*>(x) + (size_t)c * K_DIM * H4;

    // ---- Phase A: each warp owns 8 k's; scalar accumulate, one reduce per k
    const int k0 = wid * 8;
    float dots[8];
#pragma unroll
    for (int kk = 0; kk < 8; ++kk) {
        const float4* xr = xp + (k0 + kk) * H4;
        float d = 0.f;
#pragma unroll
        for (int j = 0; j < 8; ++j) {
            const int idx = lane + 32 * j;
            float4 xv = __ldg(&xr[idx]);
            float4 t4 = tsh[idx];
            d += xv.x * t4.x + xv.y * t4.y + xv.z * t4.z + xv.w * t4.w;
        }
        dots[kk] = d;
    }
#pragma unroll
    for (int kk = 0; kk < 8; ++kk) {
        float d = dots[kk];
#pragma unroll
        for (int off = 16; off; off >>= 1) d += __shfl_down_sync(0xffffffffu, d, off);
        if (lane == 0) bsh[k0 + kk] = d;
    }
    __syncthreads();

    if (t < K_DIM) {
        float bb = g_b[c * K_DIM + t] + bsh[t];
        g_b[c * K_DIM + t] = bb;
        bsh[t] = bb;
    }
    __syncthreads();

    // ---- Softmax over K=64 in warp 0 ----
    if (t < 32) {
        float b0 = bsh[t], b1 = bsh[t + 32];
        float m = fmaxf(b0, b1);
#pragma unroll
        for (int off = 16; off; off >>= 1) m = fmaxf(m, __shfl_xor_sync(0xffffffffu, m, off));
        float e0 = expf(b0 - m), e1 = expf(b1 - m);
        float ss = e0 + e1;
#pragma unroll
        for (int off = 16; off; off >>= 1) ss += __shfl_xor_sync(0xffffffffu, ss, off);
        float inv = 1.0f / ss;
        dsh[t]      = e0 * inv;
        dsh[t + 32] = e1 * inv;
    }
    __syncthreads();

    // ---- Phase B: weighted sum (x re-read, L1/L2-resident) ----
    float4 acc = make_float4(0.f, 0.f, 0.f, 0.f);
#pragma unroll 4
    for (int k = 0; k < K_DIM; ++k) {
        const float dk = dsh[k];
        float4 xv = xp[k * H4 + t];
        acc.x += dk * xv.x; acc.y += dk * xv.y;
        acc.z += dk * xv.z; acc.w += dk * xv.w;
    }
    float o[4] = {acc.x, acc.y, acc.z, acc.w};
    __nv_bfloat16 h[4], l[4];
#pragma unroll
    for (int q = 0; q < 4; ++q) bf16_split(o[q], h[q], l[q]);
    reinterpret_cast<uint2*>(g_shi)[c * H4 + t] = *reinterpret_cast<uint2*>(h);
    reinterpret_cast<uint2*>(g_slo)[c * H4 + t] = *reinterpret_cast<uint2*>(l);
}

// -------------------------------------------------------------------------
// Launch
// -------------------------------------------------------------------------
extern "C" void kernel_launch(void* const* d_in, const int* in_sizes, int n_in,
                              void* d_out, int out_size) {
    const float* x = (const float*)d_in[0];   // [512,64,1024]
    const float* W = (const float*)d_in[1];   // [1024,1024]
    float* out = (float*)d_out;               // [512,1024]

    __nv_bfloat16 *shi, *slo, *chi, *clo, *wahi, *walo, *wbhi, *wblo;
    cudaGetSymbolAddress((void**)&shi,  g_shi);
    cudaGetSymbolAddress((void**)&slo,  g_slo);
    cudaGetSymbolAddress((void**)&chi,  g_chi);
    cudaGetSymbolAddress((void**)&clo,  g_clo);
    cudaGetSymbolAddress((void**)&wahi, g_wahi);
    cudaGetSymbolAddress((void**)&walo, g_walo);
    cudaGetSymbolAddress((void**)&wbhi, g_wbhi);
    cudaGetSymbolAddress((void**)&wblo, g_wblo);

    cudaFuncSetAttribute(gemm_bf16_kernel,
                         cudaFuncAttributeMaxDynamicSharedMemorySize, SMEM_BYTES);

    const dim3 gemm_grid(H_DIM / 64, C_DIM / 128, SPLITK);  // (16, 4, 4) = 256

    split_w_kernel<<<dim3(32, 32), 256>>>(W);
    ws_uniform_kernel<<<dim3(C_DIM, 2), 128>>>(x);

    for (int iter = 0; iter < 3; ++iter) {
        // c_hat = s @ W^T   (B = bf16(W) rows [n][k]) -> g_part
        gemm_bf16_kernel<<<gemm_grid, 256, SMEM_BYTES>>>(shi, slo, wahi, walo);
        if (iter == 2)
            squash_kernel<0><<<C_DIM, 256>>>(out);
        else
            squash_kernel<1><<<C_DIM, 256>>>(nullptr);

        if (iter < 2) {
            // t = c @ W   (B = bf16(W^T) rows [n][k]) -> g_part
            gemm_bf16_kernel<<<gemm_grid, 256, SMEM_BYTES>>>(chi, clo, wbhi, wblo);
            fused_route_kernel<<<C_DIM, 256>>>(x);
        }
    }
}